// round 2
// baseline (speedup 1.0000x reference)
#include <cuda_runtime.h>

// FeatureInteraction: B=16384, F=27, D=128
// out[b] = concat(embeddings[b].flatten() (3456), triu(E E^T, k=1) (351)) -> 3807 floats

static constexpr int F      = 27;
static constexpr int F_PAD  = 28;             // pad to 4*7 so 4x4 tile loads stay in-bounds
static constexpr int D      = 128;
static constexpr int FLAT   = F * D;          // 3456
static constexpr int NPAIR  = (F * (F - 1)) / 2;  // 351
static constexpr int ROWLEN = FLAT + NPAIR;   // 3807
static constexpr int SSTRIDE = D + 1;         // 129 floats: conflict-free compute loads
static constexpr int NB     = 3;              // batch elements (warps) per block
static constexpr int THREADS = NB * 32;

__global__ void __launch_bounds__(THREADS)
fi_kernel(const float* __restrict__ in, float* __restrict__ out, int batch)
{
    __shared__ float sm[NB * F_PAD * SSTRIDE];   // 3*28*129*4 = 43344 B

    const int warp = threadIdx.x >> 5;
    const int lane = threadIdx.x & 31;
    const int b = blockIdx.x * NB + warp;
    if (b >= batch) return;

    const float* __restrict__ inb  = in  + (size_t)b * FLAT;
    float*       __restrict__ outb = out + (size_t)b * ROWLEN;
    float* smb = sm + warp * (F_PAD * SSTRIDE);

    // ---- Load phase: 864 float4 per batch element, 27 iters per lane ----
    // Write to smem (row-major, stride 129) AND stream the flat-embeddings
    // section of the output directly from registers (input read exactly once).
    #pragma unroll
    for (int it = 0; it < FLAT / 4 / 32; ++it) {
        int q = it * 32 + lane;               // float4 index within [0, 864)
        float4 v = reinterpret_cast<const float4*>(inb)[q];
        int f = q >> 5;                        // 32 float4 per feature row
        int d = (q & 31) << 2;
        float* s = smb + f * SSTRIDE + d;
        s[0] = v.x; s[1] = v.y; s[2] = v.z; s[3] = v.w;
        float* o = outb + q * 4;               // outb not 16B-aligned in general
        o[0] = v.x; o[1] = v.y; o[2] = v.z; o[3] = v.w;
    }
    __syncwarp();

    // ---- Compute phase: lane < 28 owns one 4x4 tile of the 7x7 tile grid
    // over the upper triangle of the 27x27 gram matrix. Tile loads may touch
    // pad row 27 (uninitialized); those products are never stored.
    if (lane < 28) {
        int l = lane, ti = 0, cnt = 7;
        while (l >= cnt) { l -= cnt; ++ti; --cnt; }
        const int tj = ti + l;

        const float* pi = smb + (4 * ti) * SSTRIDE;
        const float* pj = smb + (4 * tj) * SSTRIDE;

        float acc[4][4];
        #pragma unroll
        for (int r = 0; r < 4; ++r)
            #pragma unroll
            for (int c = 0; c < 4; ++c) acc[r][c] = 0.0f;

        #pragma unroll 8
        for (int d = 0; d < D; ++d) {
            float ai[4], aj[4];
            #pragma unroll
            for (int r = 0; r < 4; ++r) ai[r] = pi[r * SSTRIDE + d];
            #pragma unroll
            for (int c = 0; c < 4; ++c) aj[c] = pj[c * SSTRIDE + d];
            #pragma unroll
            for (int r = 0; r < 4; ++r)
                #pragma unroll
                for (int c = 0; c < 4; ++c)
                    acc[r][c] = fmaf(ai[r], aj[c], acc[r][c]);
        }

        // ---- Scatter into packed triu order: off(i,j) = i*F - i(i+1)/2 + (j-i-1)
        float* outp = outb + FLAT;
        #pragma unroll
        for (int r = 0; r < 4; ++r) {
            const int i = 4 * ti + r;
            #pragma unroll
            for (int c = 0; c < 4; ++c) {
                const int j = 4 * tj + c;
                if (i < j && j < F) {
                    const int off = i * F - (i * (i + 1)) / 2 + (j - i - 1);
                    outp[off] = acc[r][c];
                }
            }
        }
    }
}

extern "C" void kernel_launch(void* const* d_in, const int* in_sizes, int n_in,
                              void* d_out, int out_size)
{
    const float* in = (const float*)d_in[0];
    float* out = (float*)d_out;
    const int batch = in_sizes[0] / FLAT;      // 16384
    const int grid = (batch + NB - 1) / NB;    // 5462
    fi_kernel<<<grid, THREADS>>>(in, out, batch);
}

// round 3
// speedup vs baseline: 1.0644x; 1.0644x over previous
#include <cuda_runtime.h>

// FeatureInteraction: B=16384, F=27, D=128
// out[b] = concat(embeddings[b].flatten() (3456), triu(E E^T, k=1) (351)) -> 3807 floats
//
// R3: LDS.128 via 16B-chunk XOR swizzle (conflict-free across the 7 tile rows)
//     + packed fma.rn.f32x2 accumulation (halves FMA instruction count).

static constexpr int F      = 27;
static constexpr int F_PAD  = 28;                 // pad to 4*7 for 4x4 tiles
static constexpr int D      = 128;
static constexpr int FLAT   = F * D;              // 3456
static constexpr int NPAIR  = (F * (F - 1)) / 2;  // 351
static constexpr int ROWLEN = FLAT + NPAIR;       // 3807
static constexpr int NB     = 3;                  // batch elements (warps) per block
static constexpr int THREADS = NB * 32;

__device__ __forceinline__ unsigned long long pack2(float x, float y) {
    unsigned long long r;
    asm("mov.b64 %0, {%1, %2};" : "=l"(r) : "f"(x), "f"(y));
    return r;
}
__device__ __forceinline__ void unpack2(unsigned long long v, float& x, float& y) {
    asm("mov.b64 {%0, %1}, %2;" : "=f"(x), "=f"(y) : "l"(v));
}
__device__ __forceinline__ void ffma2(unsigned long long& acc,
                                      unsigned long long a, unsigned long long b) {
    asm("fma.rn.f32x2 %0, %1, %2, %0;" : "+l"(acc) : "l"(a), "l"(b));
}

// smem layout: row f occupies words [f*128, f*128+128); within the row the
// 16B chunk c (d = 4c..4c+3) is stored at chunk position c ^ (f>>2).
__device__ __forceinline__ int sm_off(int f, int chunk) {
    return f * D + ((chunk ^ (f >> 2)) << 2);
}

__global__ void __launch_bounds__(THREADS, 5)
fi_kernel(const float* __restrict__ in, float* __restrict__ out, int batch)
{
    __shared__ float sm[NB * F_PAD * D];          // 3*28*128*4 = 43008 B

    const int warp = threadIdx.x >> 5;
    const int lane = threadIdx.x & 31;
    const int b = blockIdx.x * NB + warp;
    if (b >= batch) return;

    const float* __restrict__ inb  = in  + (size_t)b * FLAT;
    float*       __restrict__ outb = out + (size_t)b * ROWLEN;
    float* smb = sm + warp * (F_PAD * D);

    // ---- Zero pad row 27 (read by edge tiles, never stored) ----
    {
        float4 z = make_float4(0.f, 0.f, 0.f, 0.f);
        *reinterpret_cast<float4*>(smb + 27 * D + (lane << 2)) = z;
    }

    // ---- Load phase: 864 float4 per batch element, 27 iters per lane ----
    // Stream the flat-embeddings output section directly; stage swizzled smem.
    #pragma unroll
    for (int it = 0; it < FLAT / 4 / 32; ++it) {
        int q = it * 32 + lane;                    // float4 index in [0, 864)
        float4 v = reinterpret_cast<const float4*>(inb)[q];
        int f = q >> 5;                            // 32 chunks per feature row
        int c = q & 31;                            // chunk index (d = 4c..)
        *reinterpret_cast<float4*>(smb + sm_off(f, c)) = v;
        float* o = outb + q * 4;                   // outb not 16B-aligned in general
        o[0] = v.x; o[1] = v.y; o[2] = v.z; o[3] = v.w;
    }
    __syncwarp();

    // ---- Compute: lane < 28 owns one 4x4 tile of the 7x7 tile grid over the
    // upper triangle of the 27x27 gram matrix. Per 16B chunk (4 d-values):
    // 8 LDS.128 + 32 FFMA2.
    if (lane < 28) {
        int l = lane, ti = 0, cnt = 7;
        while (l >= cnt) { l -= cnt; ++ti; --cnt; }
        const int tj = ti + l;

        unsigned long long acc[4][4];
        #pragma unroll
        for (int r = 0; r < 4; ++r)
            #pragma unroll
            for (int c = 0; c < 4; ++c) acc[r][c] = 0ull;

        const float* pi = smb + (4 * ti) * D;
        const float* pj = smb + (4 * tj) * D;

        #pragma unroll 2
        for (int c = 0; c < D / 4; ++c) {
            const int ci = (c ^ ti) << 2;
            const int cj = (c ^ tj) << 2;
            float4 ai4[4], aj4[4];
            #pragma unroll
            for (int r = 0; r < 4; ++r)
                ai4[r] = *reinterpret_cast<const float4*>(pi + r * D + ci);
            #pragma unroll
            for (int cc = 0; cc < 4; ++cc)
                aj4[cc] = *reinterpret_cast<const float4*>(pj + cc * D + cj);

            unsigned long long ailo[4], aihi[4], ajlo[4], ajhi[4];
            #pragma unroll
            for (int r = 0; r < 4; ++r) {
                ailo[r] = pack2(ai4[r].x, ai4[r].y);
                aihi[r] = pack2(ai4[r].z, ai4[r].w);
            }
            #pragma unroll
            for (int cc = 0; cc < 4; ++cc) {
                ajlo[cc] = pack2(aj4[cc].x, aj4[cc].y);
                ajhi[cc] = pack2(aj4[cc].z, aj4[cc].w);
            }
            #pragma unroll
            for (int r = 0; r < 4; ++r)
                #pragma unroll
                for (int cc = 0; cc < 4; ++cc) {
                    ffma2(acc[r][cc], ailo[r], ajlo[cc]);
                    ffma2(acc[r][cc], aihi[r], ajhi[cc]);
                }
        }

        // ---- Scatter into packed triu order: off(i,j) = i*F - i(i+1)/2 + (j-i-1)
        float* outp = outb + FLAT;
        #pragma unroll
        for (int r = 0; r < 4; ++r) {
            const int i = 4 * ti + r;
            #pragma unroll
            for (int cc = 0; cc < 4; ++cc) {
                const int j = 4 * tj + cc;
                if (i < j && j < F) {
                    float lo, hi;
                    unpack2(acc[r][cc], lo, hi);
                    const int off = i * F - (i * (i + 1)) / 2 + (j - i - 1);
                    outp[off] = lo + hi;
                }
            }
        }
    }
}

extern "C" void kernel_launch(void* const* d_in, const int* in_sizes, int n_in,
                              void* d_out, int out_size)
{
    const float* in = (const float*)d_in[0];
    float* out = (float*)d_out;
    const int batch = in_sizes[0] / FLAT;      // 16384
    const int grid = (batch + NB - 1) / NB;    // 5462
    fi_kernel<<<grid, THREADS>>>(in, out, batch);
}